// round 4
// baseline (speedup 1.0000x reference)
#include <cuda_runtime.h>

// QBlock W4A8: x -> qconv1x1 -> qdw3x3 -> prelu -> qconv1x1 -> qdw3x3 -> prelu -> +x
// B=16, C=64, H=W=256, fp32 NCHW.

#define B_ 16
#define C_ 64
#define H_ 256
#define W_ 256
#define HW_ 65536
#define CHW_ 4194304
#define NTOT_ 67108864
#define NPOS_ 1048576

#define MAGICF 12582912.0f          // 2^23 + 2^22 : RNE integer extraction

__device__ float g_buf1[NTOT_];
__device__ float g_buf2[NTOT_];
__device__ unsigned int g_amax[4];   // 0: x, 1: y1, 2: y3, 3: y4
__device__ float g_wscale[4];
__device__ int   g_wp1[1024];        // 64 co x 16 packed int8x4 (ci)
__device__ int   g_wp2[1024];
__device__ float g_wf1[576];         // dequantized dw weights
__device__ float g_wf2[576];

// clamp+RNE in float domain; low byte of result bits == int8 quantized value
__device__ __forceinline__ unsigned int qbits(float v, float inv) {
    float m = v * inv;
    m = fminf(fmaxf(m, -127.0f), 127.0f);
    return __float_as_uint(m + MAGICF);
}
// quantize-dequantize, all on FP pipe
__device__ __forceinline__ float qdq(float v, float inv, float scale) {
    float m = v * inv;
    m = fminf(fmaxf(m, -127.0f), 127.0f);
    float t = m + MAGICF;
    return (t - MAGICF) * scale;
}

__global__ void k_init() {
    if (threadIdx.x < 4) g_amax[threadIdx.x] = 0u;
}

__global__ void __launch_bounds__(256) k_wquant(const float* __restrict__ wp1,
                                                const float* __restrict__ wf1,
                                                const float* __restrict__ wp2,
                                                const float* __restrict__ wf2) {
    __shared__ float red[256];
    int tid = threadIdx.x;
    int wsel = blockIdx.x;
    const float* src = (wsel == 0) ? wp1 : (wsel == 1) ? wf1 : (wsel == 2) ? wp2 : wf2;
    int n = (wsel == 0 || wsel == 2) ? 4096 : 576;

    float m = 0.f;
    for (int i = tid; i < n; i += 256) m = fmaxf(m, fabsf(src[i]));
    red[tid] = m; __syncthreads();
    for (int s = 128; s > 0; s >>= 1) {
        if (tid < s) red[tid] = fmaxf(red[tid], red[tid + s]);
        __syncthreads();
    }
    float scale = red[0] / 7.0f + 1e-12f;
    if (tid == 0) g_wscale[wsel] = scale;

    if (wsel == 0 || wsel == 2) {
        int* dst = (wsel == 0) ? g_wp1 : g_wp2;
        for (int i = tid; i < 1024; i += 256) {
            int co = i >> 4, k = i & 15;
            unsigned int packed = 0;
            #pragma unroll
            for (int j = 0; j < 4; j++) {
                float v = src[co * 64 + k * 4 + j];
                int q = __float2int_rn(v / scale);
                q = max(-7, min(7, q));
                packed |= ((unsigned int)(q & 0xFF)) << (8 * j);
            }
            dst[i] = (int)packed;
        }
    } else {
        float* dst = (wsel == 1) ? g_wf1 : g_wf2;
        for (int i = tid; i < n; i += 256) {
            float q = rintf(src[i] / scale);
            q = fmaxf(-7.f, fminf(7.f, q));
            dst[i] = q * scale;
        }
    }
}

__global__ void __launch_bounds__(256) k_amax_x(const float4* __restrict__ in) {
    __shared__ unsigned int wred[8];
    int tid = threadIdx.x;
    float m = 0.f;
    int n4 = NTOT_ / 4;
    for (int i = blockIdx.x * 256 + tid; i < n4; i += gridDim.x * 256) {
        float4 v = in[i];
        m = fmaxf(m, fmaxf(fmaxf(fabsf(v.x), fabsf(v.y)), fmaxf(fabsf(v.z), fabsf(v.w))));
    }
    unsigned int u = __reduce_max_sync(0xffffffffu, __float_as_uint(m));
    if ((tid & 31) == 0) wred[tid >> 5] = u;
    __syncthreads();
    if (tid < 8) {
        unsigned int v = wred[tid];
        #pragma unroll
        for (int s = 4; s > 0; s >>= 1) v = max(v, __shfl_down_sync(0xffu, v, s));
        if (tid == 0) atomicMax(&g_amax[0], v);
    }
}

// 1x1 conv, int8 x int4 dp4a, 2 pixels per thread (float2 I/O), occ-capped.
__global__ void __launch_bounds__(256, 4) k_conv1x1(const float* __restrict__ ext_in,
                                                    int in_sel, int wp_sel,
                                                    int s_in, int s_w, int s_out) {
    __shared__ int ws[1024];
    __shared__ unsigned int wred[8];
    int tid = threadIdx.x;
    const int* wpack = (wp_sel == 0) ? g_wp1 : g_wp2;
    for (int i = tid; i < 1024; i += 256) ws[i] = wpack[i];

    float amax_in = __uint_as_float(g_amax[s_in]);
    float scale_in = amax_in / 127.0f + 1e-12f;
    float inv_in = 1.0f / scale_in;
    float out_scale = scale_in * g_wscale[s_w];
    __syncthreads();

    const float* in = (in_sel == 0) ? ext_in : g_buf2;
    int p2 = blockIdx.x * 256 + tid;        // float2 index over (b,hw)
    int b = p2 >> 15;                        // 32768 float2 per plane
    int hw2 = p2 & 32767;
    const float2* in2 = (const float2*)in + (size_t)b * (CHW_ / 2) + hw2;

    int xq0[16], xq1[16];
    #pragma unroll
    for (int k = 0; k < 16; k++) {
        unsigned int a0, a1, a2, a3, b0, b1, b2, b3;
        float2 v0 = in2[(size_t)(k * 4 + 0) * 32768];
        float2 v1 = in2[(size_t)(k * 4 + 1) * 32768];
        float2 v2 = in2[(size_t)(k * 4 + 2) * 32768];
        float2 v3 = in2[(size_t)(k * 4 + 3) * 32768];
        a0 = qbits(v0.x, inv_in); b0 = qbits(v0.y, inv_in);
        a1 = qbits(v1.x, inv_in); b1 = qbits(v1.y, inv_in);
        a2 = qbits(v2.x, inv_in); b2 = qbits(v2.y, inv_in);
        a3 = qbits(v3.x, inv_in); b3 = qbits(v3.y, inv_in);
        unsigned int lo = __byte_perm(a0, a1, 0x0040);   // [a0.b0, a1.b0]
        unsigned int hi = __byte_perm(a2, a3, 0x0040);
        xq0[k] = (int)__byte_perm(lo, hi, 0x5410);
        lo = __byte_perm(b0, b1, 0x0040);
        hi = __byte_perm(b2, b3, 0x0040);
        xq1[k] = (int)__byte_perm(lo, hi, 0x5410);
    }

    float2* op2 = (float2*)g_buf1 + (size_t)b * (CHW_ / 2) + hw2;
    float m = 0.f;
    #pragma unroll 4
    for (int co = 0; co < 64; co++) {
        int a0 = 0, a1 = 0;
        #pragma unroll
        for (int k = 0; k < 16; k++) {
            int w = ws[co * 16 + k];
            a0 = __dp4a(xq0[k], w, a0);
            a1 = __dp4a(xq1[k], w, a1);
        }
        float2 y;
        y.x = (float)a0 * out_scale;
        y.y = (float)a1 * out_scale;
        op2[(size_t)co * 32768] = y;
        m = fmaxf(m, fmaxf(fabsf(y.x), fabsf(y.y)));
    }

    unsigned int u = __reduce_max_sync(0xffffffffu, __float_as_uint(m));
    if ((tid & 31) == 0) wred[tid >> 5] = u;
    __syncthreads();
    if (tid < 8) {
        unsigned int v = wred[tid];
        #pragma unroll
        for (int s = 4; s > 0; s >>= 1) v = max(v, __shfl_down_sync(0xffu, v, s));
        if (tid == 0) atomicMax(&g_amax[s_out], v);
    }
}

// Depthwise 3x3 (pad 1) + PReLU [+ residual]. Tile: full row (W=256) x 32 rows.
#define DWROWS 32
__global__ void __launch_bounds__(256) k_dw3x3(float* __restrict__ ext_out,
                                               const float* __restrict__ resid,
                                               const float* __restrict__ alpha,
                                               int wf_sel, int s_in, int s_out) {
    __shared__ float sh[DWROWS + 2][258];    // col c at [.][c+1]; 0/257 zero
    __shared__ unsigned int wred[8];

    int bc = blockIdx.y;                      // b*64 + c
    int ch = bc & 63;
    int tid = threadIdx.x;
    int y0 = blockIdx.x * DWROWS;

    const float* wf = (wf_sel == 0) ? g_wf1 : g_wf2;
    float w0 = wf[ch * 9 + 0], w1 = wf[ch * 9 + 1], w2 = wf[ch * 9 + 2];
    float w3 = wf[ch * 9 + 3], w4 = wf[ch * 9 + 4], w5 = wf[ch * 9 + 5];
    float w6 = wf[ch * 9 + 6], w7 = wf[ch * 9 + 7], w8 = wf[ch * 9 + 8];
    float a = alpha[ch];

    float amax_in = __uint_as_float(g_amax[s_in]);
    float scale_in = amax_in / 127.0f + 1e-12f;
    float inv_in = 1.0f / scale_in;

    const float4* plane4 = (const float4*)(g_buf1 + (size_t)bc * HW_);

    if (tid < DWROWS + 2) sh[tid][0] = 0.f;
    else if (tid < 2 * (DWROWS + 2)) sh[tid - (DWROWS + 2)][257] = 0.f;

    for (int i = tid; i < (DWROWS + 2) * 64; i += 256) {
        int r = i >> 6, c4 = i & 63;
        int gy = y0 + r - 1;
        float v0 = 0.f, v1 = 0.f, v2 = 0.f, v3 = 0.f;
        if (gy >= 0 && gy < H_) {
            float4 v = plane4[gy * 64 + c4];
            v0 = qdq(v.x, inv_in, scale_in);
            v1 = qdq(v.y, inv_in, scale_in);
            v2 = qdq(v.z, inv_in, scale_in);
            v3 = qdq(v.w, inv_in, scale_in);
        }
        int c = c4 * 4 + 1;
        sh[r][c] = v0; sh[r][c + 1] = v1; sh[r][c + 2] = v2; sh[r][c + 3] = v3;
    }
    __syncthreads();

    int col = tid;                            // output column 0..255
    float t00 = sh[0][col], t01 = sh[0][col + 1], t02 = sh[0][col + 2];
    float t10 = sh[1][col], t11 = sh[1][col + 1], t12 = sh[1][col + 2];

    float* out = ext_out ? ext_out : g_buf2;
    size_t obase = (size_t)bc * HW_ + (size_t)y0 * W_ + col;
    float m = 0.f;

    #pragma unroll 8
    for (int r = 0; r < DWROWS; r++) {
        float t20 = sh[r + 2][col], t21 = sh[r + 2][col + 1], t22 = sh[r + 2][col + 2];
        float acc = t00 * w0;
        acc = fmaf(t01, w1, acc); acc = fmaf(t02, w2, acc);
        acc = fmaf(t10, w3, acc); acc = fmaf(t11, w4, acc);
        acc = fmaf(t12, w5, acc); acc = fmaf(t20, w6, acc);
        acc = fmaf(t21, w7, acc); acc = fmaf(t22, w8, acc);
        float v = fmaxf(acc, 0.f) + a * fminf(acc, 0.f);   // PReLU
        size_t oidx = obase + (size_t)r * W_;
        if (resid) v += resid[oidx];
        out[oidx] = v;
        m = fmaxf(m, fabsf(v));
        t00 = t10; t01 = t11; t02 = t12;
        t10 = t20; t11 = t21; t12 = t22;
    }

    if (s_out >= 0) {
        unsigned int u = __reduce_max_sync(0xffffffffu, __float_as_uint(m));
        if ((tid & 31) == 0) wred[tid >> 5] = u;
        __syncthreads();
        if (tid < 8) {
            unsigned int v = wred[tid];
            #pragma unroll
            for (int s = 4; s > 0; s >>= 1) v = max(v, __shfl_down_sync(0xffu, v, s));
            if (tid == 0) atomicMax(&g_amax[s_out], v);
        }
    }
}

extern "C" void kernel_launch(void* const* d_in, const int* in_sizes, int n_in,
                              void* d_out, int out_size) {
    const float* x   = (const float*)d_in[0];
    const float* wp1 = (const float*)d_in[1];
    const float* wf1 = (const float*)d_in[2];
    const float* wp2 = (const float*)d_in[3];
    const float* wf2 = (const float*)d_in[4];
    const float* a1  = (const float*)d_in[5];
    const float* a2  = (const float*)d_in[6];
    float* out = (float*)d_out;

    dim3 dwGrid(H_ / DWROWS, B_ * C_);

    k_init<<<1, 32>>>();
    k_wquant<<<4, 256>>>(wp1, wf1, wp2, wf2);
    k_amax_x<<<8192, 256>>>((const float4*)x);

    k_conv1x1<<<NPOS_ / 512, 256>>>(x, 0, 0, /*s_in=*/0, /*s_w=*/0, /*s_out=*/1);
    k_dw3x3<<<dwGrid, 256>>>(nullptr, nullptr, a1, 0, /*s_in=*/1, /*s_out=*/2);
    k_conv1x1<<<NPOS_ / 512, 256>>>(x, 1, 1, /*s_in=*/2, /*s_w=*/2, /*s_out=*/3);
    k_dw3x3<<<dwGrid, 256>>>(out, x, a2, 1, /*s_in=*/3, /*s_out=*/-1);
}

// round 5
// speedup vs baseline: 1.1595x; 1.1595x over previous
#include <cuda_runtime.h>

// QBlock W4A8: x -> qconv1x1 -> qdw3x3 -> prelu -> qconv1x1 -> qdw3x3 -> prelu -> +x
// B=16, C=64, H=W=256, fp32 NCHW.
// conv1x1 via IMMA mma.sync.m16n8k32.s8 (exact integer accumulation).

#define B_ 16
#define C_ 64
#define H_ 256
#define W_ 256
#define HW_ 65536
#define CHW_ 4194304
#define NTOT_ 67108864
#define NPOS_ 1048576

#define MAGICF 12582912.0f          // 2^23 + 2^22 : RNE integer extraction

__device__ float g_buf1[NTOT_];
__device__ float g_buf2[NTOT_];
__device__ unsigned int g_amax[4];   // 0: x, 1: y1, 2: y3, 3: y4
__device__ float g_wscale[4];
__device__ int   g_wp1[1024];        // 64 co x 16 packed int8x4 (ci)
__device__ int   g_wp2[1024];
__device__ float g_wf1[576];         // dequantized dw weights
__device__ float g_wf2[576];

// clamp+RNE in float domain; low byte of result bits == int8 (two's complement)
__device__ __forceinline__ unsigned int qbits(float v, float inv) {
    float m = v * inv;
    m = fminf(fmaxf(m, -127.0f), 127.0f);
    return __float_as_uint(m + MAGICF);
}
// quantize-dequantize, all on FP pipe
__device__ __forceinline__ float qdq(float v, float inv, float scale) {
    float m = v * inv;
    m = fminf(fmaxf(m, -127.0f), 127.0f);
    float t = m + MAGICF;
    return (t - MAGICF) * scale;
}

__device__ __forceinline__ void mma_s8(int& c0, int& c1, int& c2, int& c3,
                                       int a0, int a1, int a2, int a3,
                                       int b0, int b1) {
    asm volatile(
        "mma.sync.aligned.m16n8k32.row.col.s32.s8.s8.s32 "
        "{%0,%1,%2,%3}, {%4,%5,%6,%7}, {%8,%9}, {%0,%1,%2,%3};"
        : "+r"(c0), "+r"(c1), "+r"(c2), "+r"(c3)
        : "r"(a0), "r"(a1), "r"(a2), "r"(a3), "r"(b0), "r"(b1));
}

__global__ void k_init() {
    if (threadIdx.x < 4) g_amax[threadIdx.x] = 0u;
}

__global__ void __launch_bounds__(256) k_wquant(const float* __restrict__ wp1,
                                                const float* __restrict__ wf1,
                                                const float* __restrict__ wp2,
                                                const float* __restrict__ wf2) {
    __shared__ float red[256];
    int tid = threadIdx.x;
    int wsel = blockIdx.x;
    const float* src = (wsel == 0) ? wp1 : (wsel == 1) ? wf1 : (wsel == 2) ? wp2 : wf2;
    int n = (wsel == 0 || wsel == 2) ? 4096 : 576;

    float m = 0.f;
    for (int i = tid; i < n; i += 256) m = fmaxf(m, fabsf(src[i]));
    red[tid] = m; __syncthreads();
    for (int s = 128; s > 0; s >>= 1) {
        if (tid < s) red[tid] = fmaxf(red[tid], red[tid + s]);
        __syncthreads();
    }
    float scale = red[0] / 7.0f + 1e-12f;
    if (tid == 0) g_wscale[wsel] = scale;

    if (wsel == 0 || wsel == 2) {
        int* dst = (wsel == 0) ? g_wp1 : g_wp2;
        for (int i = tid; i < 1024; i += 256) {
            int co = i >> 4, k = i & 15;
            unsigned int packed = 0;
            #pragma unroll
            for (int j = 0; j < 4; j++) {
                float v = src[co * 64 + k * 4 + j];
                int q = __float2int_rn(v / scale);
                q = max(-7, min(7, q));
                packed |= ((unsigned int)(q & 0xFF)) << (8 * j);
            }
            dst[i] = (int)packed;
        }
    } else {
        float* dst = (wsel == 1) ? g_wf1 : g_wf2;
        for (int i = tid; i < n; i += 256) {
            float q = rintf(src[i] / scale);
            q = fmaxf(-7.f, fminf(7.f, q));
            dst[i] = q * scale;
        }
    }
}

__global__ void __launch_bounds__(256) k_amax_x(const float4* __restrict__ in) {
    __shared__ unsigned int wred[8];
    int tid = threadIdx.x;
    float m = 0.f;
    int n4 = NTOT_ / 4;
    for (int i = blockIdx.x * 256 + tid; i < n4; i += gridDim.x * 256) {
        float4 v = in[i];
        m = fmaxf(m, fmaxf(fmaxf(fabsf(v.x), fabsf(v.y)), fmaxf(fabsf(v.z), fabsf(v.w))));
    }
    unsigned int u = __reduce_max_sync(0xffffffffu, __float_as_uint(m));
    if ((tid & 31) == 0) wred[tid >> 5] = u;
    __syncthreads();
    if (tid < 8) {
        unsigned int v = wred[tid];
        #pragma unroll
        for (int s = 4; s > 0; s >>= 1) v = max(v, __shfl_down_sync(0xffu, v, s));
        if (tid == 0) atomicMax(&g_amax[0], v);
    }
}

// 1x1 conv via IMMA. Block = 256 threads = 8 warps = 256 pixels (1 px/thread
// for quantize phase; warp computes its 32 pixels x 64 co via mma).
__global__ void __launch_bounds__(256) k_conv1x1(const float* __restrict__ ext_in,
                                                 int in_sel, int wp_sel,
                                                 int s_in, int s_w, int s_out) {
    __shared__ int ws[1024];
    __shared__ unsigned int wred[8];
    int tid = threadIdx.x;
    int l = tid & 31;
    const int* wpack = (wp_sel == 0) ? g_wp1 : g_wp2;
    for (int i = tid; i < 1024; i += 256) ws[i] = wpack[i];

    float amax_in = __uint_as_float(g_amax[s_in]);
    float scale_in = amax_in / 127.0f + 1e-12f;
    float inv_in = 1.0f / scale_in;
    float out_scale = scale_in * g_wscale[s_w];
    __syncthreads();

    const float* in = (in_sel == 0) ? ext_in : g_buf2;
    int p = blockIdx.x * 256 + tid;          // this thread's pixel
    int b = p >> 16;                          // whole block shares b (256 | 65536)
    int hw = p & 65535;
    const float* xin = in + (size_t)b * CHW_ + hw;

    // quantize 64 channels -> 16 packed int8x4 words (channel-major in word)
    int w[16];
    #pragma unroll
    for (int k = 0; k < 16; k++) {
        unsigned int q0 = qbits(xin[(size_t)(k * 4 + 0) * HW_], inv_in);
        unsigned int q1 = qbits(xin[(size_t)(k * 4 + 1) * HW_], inv_in);
        unsigned int q2 = qbits(xin[(size_t)(k * 4 + 2) * HW_], inv_in);
        unsigned int q3 = qbits(xin[(size_t)(k * 4 + 3) * HW_], inv_in);
        unsigned int lo = __byte_perm(q0, q1, 0x0040);
        unsigned int hi = __byte_perm(q2, q3, 0x0040);
        w[k] = (int)__byte_perm(lo, hi, 0x5410);
    }

    // Build A fragments by warp shuffle.
    // a[mt][kt][0..3]: m16n8k32 A (row-major 16x32 s8):
    //   a0: row l/4,   ci-words kt*8 + (l%4)
    //   a1: row l/4+8, ci-words kt*8 + (l%4)
    //   a2: row l/4,   ci-words kt*8 + 4 + (l%4)
    //   a3: row l/4+8, ci-words kt*8 + 4 + (l%4)
    // rows are pixels (warp-local): mt*16 + row.
    int afr[2][2][4];
    int srclo = (l >> 2);
    #pragma unroll
    for (int mt = 0; mt < 2; mt++) {
        #pragma unroll
        for (int kt = 0; kt < 2; kt++) {
            int a0 = 0, a1 = 0, a2 = 0, a3 = 0;
            #pragma unroll
            for (int j = 0; j < 4; j++) {
                int t0 = __shfl_sync(0xffffffffu, w[kt * 8 + j],     mt * 16 + srclo);
                int t1 = __shfl_sync(0xffffffffu, w[kt * 8 + j],     mt * 16 + srclo + 8);
                int t2 = __shfl_sync(0xffffffffu, w[kt * 8 + 4 + j], mt * 16 + srclo);
                int t3 = __shfl_sync(0xffffffffu, w[kt * 8 + 4 + j], mt * 16 + srclo + 8);
                if ((l & 3) == j) { a0 = t0; a1 = t1; a2 = t2; a3 = t3; }
            }
            afr[mt][kt][0] = a0; afr[mt][kt][1] = a1;
            afr[mt][kt][2] = a2; afr[mt][kt][3] = a3;
        }
    }

    int warpPix = (tid >> 5) * 32;           // warp-local pixel base (within block)
    int blkBase = blockIdx.x * 256;
    float m = 0.f;

    // Two n-halves of 32 output channels each: 2mt x 4nt C tiles (32 regs)
    #pragma unroll
    for (int nh = 0; nh < 2; nh++) {
        int cfr[2][4][4];
        #pragma unroll
        for (int mt = 0; mt < 2; mt++)
            #pragma unroll
            for (int nt = 0; nt < 4; nt++) {
                cfr[mt][nt][0] = 0; cfr[mt][nt][1] = 0;
                cfr[mt][nt][2] = 0; cfr[mt][nt][3] = 0;
            }

        #pragma unroll
        for (int nt = 0; nt < 4; nt++) {
            int co = nh * 32 + nt * 8 + (l >> 2);      // B col for this lane
            #pragma unroll
            for (int kt = 0; kt < 2; kt++) {
                // B (col-major 32x8 s8): b0 rows 4(l%4).., b1 rows 16+4(l%4)..
                int b0 = ws[co * 16 + kt * 8 + (l & 3)];
                int b1 = ws[co * 16 + kt * 8 + 4 + (l & 3)];
                #pragma unroll
                for (int mt = 0; mt < 2; mt++) {
                    mma_s8(cfr[mt][nt][0], cfr[mt][nt][1], cfr[mt][nt][2], cfr[mt][nt][3],
                           afr[mt][kt][0], afr[mt][kt][1], afr[mt][kt][2], afr[mt][kt][3],
                           b0, b1);
                }
            }
        }

        // store: C m16n8 s32 frag: c0:(row l/4, col 2(l%4)) c1:(.., col+1)
        //        c2:(row l/4+8, col) c3:(row l/4+8, col+1)
        #pragma unroll
        for (int mt = 0; mt < 2; mt++) {
            int pix0 = blkBase + warpPix + mt * 16 + (l >> 2);   // global pixel
            int hw0 = pix0 & 65535;
            #pragma unroll
            for (int nt = 0; nt < 4; nt++) {
                int co = nh * 32 + nt * 8 + 2 * (l & 3);
                float* base0 = g_buf1 + (size_t)b * CHW_ + (size_t)co * HW_;
                float y0 = (float)cfr[mt][nt][0] * out_scale;
                float y1 = (float)cfr[mt][nt][1] * out_scale;
                float y2 = (float)cfr[mt][nt][2] * out_scale;
                float y3 = (float)cfr[mt][nt][3] * out_scale;
                base0[hw0]            = y0;
                base0[HW_ + hw0]      = y1;
                base0[hw0 + 8]        = y2;
                base0[HW_ + hw0 + 8]  = y3;
                m = fmaxf(m, fmaxf(fmaxf(fabsf(y0), fabsf(y1)), fmaxf(fabsf(y2), fabsf(y3))));
            }
        }
    }

    unsigned int u = __reduce_max_sync(0xffffffffu, __float_as_uint(m));
    if ((tid & 31) == 0) wred[tid >> 5] = u;
    __syncthreads();
    if (tid < 8) {
        unsigned int v = wred[tid];
        #pragma unroll
        for (int s = 4; s > 0; s >>= 1) v = max(v, __shfl_down_sync(0xffu, v, s));
        if (tid == 0) atomicMax(&g_amax[s_out], v);
    }
}

// Depthwise 3x3 (pad 1) + PReLU [+ residual]. Tile: full row (W=256) x 16 rows.
// (R3-proven configuration.)
__global__ void __launch_bounds__(256) k_dw3x3(float* __restrict__ ext_out,
                                               const float* __restrict__ resid,
                                               const float* __restrict__ alpha,
                                               int wf_sel, int s_in, int s_out) {
    __shared__ float sh[18][258];            // col c at [.][c+1]; 0/257 zero
    __shared__ unsigned int wred[8];

    int bc = blockIdx.y;                      // b*64 + c
    int ch = bc & 63;
    int tid = threadIdx.x;
    int y0 = blockIdx.x * 16;

    const float* wf = (wf_sel == 0) ? g_wf1 : g_wf2;
    float w0 = wf[ch * 9 + 0], w1 = wf[ch * 9 + 1], w2 = wf[ch * 9 + 2];
    float w3 = wf[ch * 9 + 3], w4 = wf[ch * 9 + 4], w5 = wf[ch * 9 + 5];
    float w6 = wf[ch * 9 + 6], w7 = wf[ch * 9 + 7], w8 = wf[ch * 9 + 8];
    float a = alpha[ch];

    float amax_in = __uint_as_float(g_amax[s_in]);
    float scale_in = amax_in / 127.0f + 1e-12f;
    float inv_in = 1.0f / scale_in;

    const float4* plane4 = (const float4*)(g_buf1 + (size_t)bc * HW_);

    if (tid < 18) sh[tid][0] = 0.f;
    else if (tid < 36) sh[tid - 18][257] = 0.f;

    for (int i = tid; i < 18 * 64; i += 256) {
        int r = i >> 6, c4 = i & 63;
        int gy = y0 + r - 1;
        float v0 = 0.f, v1 = 0.f, v2 = 0.f, v3 = 0.f;
        if (gy >= 0 && gy < H_) {
            float4 v = plane4[gy * 64 + c4];
            v0 = qdq(v.x, inv_in, scale_in);
            v1 = qdq(v.y, inv_in, scale_in);
            v2 = qdq(v.z, inv_in, scale_in);
            v3 = qdq(v.w, inv_in, scale_in);
        }
        int c = c4 * 4 + 1;
        sh[r][c] = v0; sh[r][c + 1] = v1; sh[r][c + 2] = v2; sh[r][c + 3] = v3;
    }
    __syncthreads();

    int col = tid;                            // output column 0..255
    float t00 = sh[0][col], t01 = sh[0][col + 1], t02 = sh[0][col + 2];
    float t10 = sh[1][col], t11 = sh[1][col + 1], t12 = sh[1][col + 2];

    float* out = ext_out ? ext_out : g_buf2;
    size_t obase = (size_t)bc * HW_ + (size_t)y0 * W_ + col;
    float m = 0.f;

    #pragma unroll
    for (int r = 0; r < 16; r++) {
        float t20 = sh[r + 2][col], t21 = sh[r + 2][col + 1], t22 = sh[r + 2][col + 2];
        float acc = t00 * w0;
        acc = fmaf(t01, w1, acc); acc = fmaf(t02, w2, acc);
        acc = fmaf(t10, w3, acc); acc = fmaf(t11, w4, acc);
        acc = fmaf(t12, w5, acc); acc = fmaf(t20, w6, acc);
        acc = fmaf(t21, w7, acc); acc = fmaf(t22, w8, acc);
        float v = fmaxf(acc, 0.f) + a * fminf(acc, 0.f);   // PReLU
        size_t oidx = obase + (size_t)r * W_;
        if (resid) v += resid[oidx];
        out[oidx] = v;
        m = fmaxf(m, fabsf(v));
        t00 = t10; t01 = t11; t02 = t12;
        t10 = t20; t11 = t21; t12 = t22;
    }

    if (s_out >= 0) {
        unsigned int u = __reduce_max_sync(0xffffffffu, __float_as_uint(m));
        if ((tid & 31) == 0) wred[tid >> 5] = u;
        __syncthreads();
        if (tid < 8) {
            unsigned int v = wred[tid];
            #pragma unroll
            for (int s = 4; s > 0; s >>= 1) v = max(v, __shfl_down_sync(0xffu, v, s));
            if (tid == 0) atomicMax(&g_amax[s_out], v);
        }
    }
}

extern "C" void kernel_launch(void* const* d_in, const int* in_sizes, int n_in,
                              void* d_out, int out_size) {
    const float* x   = (const float*)d_in[0];
    const float* wp1 = (const float*)d_in[1];
    const float* wf1 = (const float*)d_in[2];
    const float* wp2 = (const float*)d_in[3];
    const float* wf2 = (const float*)d_in[4];
    const float* a1  = (const float*)d_in[5];
    const float* a2  = (const float*)d_in[6];
    float* out = (float*)d_out;

    dim3 dwGrid(H_ / 16, B_ * C_);

    k_init<<<1, 32>>>();
    k_wquant<<<4, 256>>>(wp1, wf1, wp2, wf2);
    k_amax_x<<<8192, 256>>>((const float4*)x);

    k_conv1x1<<<NPOS_ / 256, 256>>>(x, 0, 0, /*s_in=*/0, /*s_w=*/0, /*s_out=*/1);
    k_dw3x3<<<dwGrid, 256>>>(nullptr, nullptr, a1, 0, /*s_in=*/1, /*s_out=*/2);
    k_conv1x1<<<NPOS_ / 256, 256>>>(x, 1, 1, /*s_in=*/2, /*s_w=*/2, /*s_out=*/3);
    k_dw3x3<<<dwGrid, 256>>>(out, x, a2, 1, /*s_in=*/3, /*s_out=*/-1);
}